// round 16
// baseline (speedup 1.0000x reference)
#include <cuda_runtime.h>
#include <cuda_fp16.h>

#define U_CNT 100000
#define I_CNT 50000
#define N_CNT 150000
#define DIM   64
#define NNZ_CNT 3200000
#define B_CNT 4096
#define NBW   ((N_CNT + 31) / 32)
#define HIST_BLKS (NNZ_CNT / 1024)           // 3125
#define PREP_BLKS ((2 * B_CNT + 255) / 256)  // 32

// ---- scratch (__device__ globals; allocation-free rule) ----
__device__ __align__(16) __half g_egoh[N_CNT * DIM];
__device__ __align__(16) __half g_cur1h[N_CNT * DIM];
__device__ __align__(16) __half g_cur2h[N_CNT * DIM];
__device__ __align__(16) __half g_cur3h[N_CNT * DIM];

__device__ unsigned g_s3_bits[NBW];
__device__ unsigned g_s2_bits[NBW];

// compact CSR
__device__ __align__(16) unsigned g_deg[N_CNT];
__device__ __align__(16) unsigned g_offs[N_CNT];
__device__ __align__(16) unsigned g_cursor[N_CNT];
__device__ unsigned g_total;
__device__ __align__(16) int2     g_edges[NNZ_CNT];   // {col, val as replicated half2}

__device__ __forceinline__ bool test_bit(const unsigned* bits, int n) {
    return (__ldg(bits + (n >> 5)) >> (n & 31)) & 1u;
}

// ---- 1. init: convert ego to fp16, zero deg/bitmaps/total (r10-identical) ----
__global__ void init_kernel(const float* __restrict__ ue,
                            const float* __restrict__ ie) {
    unsigned t = blockIdx.x * blockDim.x + threadIdx.x;
    const unsigned n16 = (unsigned)N_CNT * DIM / 8;
    if (t < n16) {
        const unsigned UF4 = (unsigned)U_CNT * DIM / 4;
        unsigned f0 = 2u * t, f1 = 2u * t + 1u;
        float4 a = (f0 < UF4) ? __ldg(reinterpret_cast<const float4*>(ue) + f0)
                              : __ldg(reinterpret_cast<const float4*>(ie) + (f0 - UF4));
        float4 b = (f1 < UF4) ? __ldg(reinterpret_cast<const float4*>(ue) + f1)
                              : __ldg(reinterpret_cast<const float4*>(ie) + (f1 - UF4));
        uint4 o;
        __half2 h;
        h = __floats2half2_rn(a.x, a.y); o.x = *reinterpret_cast<unsigned*>(&h);
        h = __floats2half2_rn(a.z, a.w); o.y = *reinterpret_cast<unsigned*>(&h);
        h = __floats2half2_rn(b.x, b.y); o.z = *reinterpret_cast<unsigned*>(&h);
        h = __floats2half2_rn(b.z, b.w); o.w = *reinterpret_cast<unsigned*>(&h);
        reinterpret_cast<uint4*>(g_egoh)[t] = o;
    }
    if (t < N_CNT / 4)
        reinterpret_cast<uint4*>(g_deg)[t] = make_uint4(0u, 0u, 0u, 0u);
    if (t < NBW) { g_s3_bits[t] = 0u; g_s2_bits[t] = 0u; }
    if (t == 0) g_total = 0u;
}

// ---- 2. prep + hist merged (r10-identical) ----
__global__ void prep_hist_kernel(const int* __restrict__ rows,
                                 const int* __restrict__ users,
                                 const int* __restrict__ items) {
    unsigned b = blockIdx.x;
    if (b < HIST_BLKS) {
        unsigned q = b * 256u + threadIdx.x;
        int4 r4 = __ldg(reinterpret_cast<const int4*>(rows) + q);
        atomicAdd(&g_deg[r4.x], 1u);
        atomicAdd(&g_deg[r4.y], 1u);
        atomicAdd(&g_deg[r4.z], 1u);
        atomicAdd(&g_deg[r4.w], 1u);
    } else {
        unsigned t = (b - HIST_BLKS) * 256u + threadIdx.x;
        if (t < 2u * B_CNT) {
            int node = (t < B_CNT) ? __ldg(users + t)
                                   : (U_CNT + __ldg(items + (t - B_CNT)));
            atomicOr(&g_s3_bits[node >> 5], 1u << (node & 31));
            atomicOr(&g_s2_bits[node >> 5], 1u << (node & 31));
        }
    }
}

// ---- 3. scan (r10-identical) ----
__global__ void scan_kernel() {
    __shared__ unsigned wsum[32];
    __shared__ unsigned s_base;
    int tid = threadIdx.x, lane = tid & 31, wid = tid >> 5;
    unsigned i0 = blockIdx.x * 4096u + tid * 4u;
    uint4 d = make_uint4(0u, 0u, 0u, 0u);
    if (i0 < N_CNT) d = *reinterpret_cast<const uint4*>(&g_deg[i0]);
    unsigned t1 = d.x, t2 = d.x + d.y, t3 = d.x + d.y + d.z;
    unsigned tsum = t3 + d.w;
    unsigned inc = tsum;
    #pragma unroll
    for (int o = 1; o < 32; o <<= 1) {
        unsigned v = __shfl_up_sync(0xffffffffu, inc, o);
        if (lane >= o) inc += v;
    }
    unsigned texcl = inc - tsum;
    if (lane == 31) wsum[wid] = inc;
    __syncthreads();
    if (wid == 0) {
        unsigned ws = wsum[lane];
        unsigned wi = ws;
        #pragma unroll
        for (int o = 1; o < 32; o <<= 1) {
            unsigned v = __shfl_up_sync(0xffffffffu, wi, o);
            if (lane >= o) wi += v;
        }
        if (lane == 31) s_base = atomicAdd(&g_total, wi);
        wsum[lane] = wi - ws;
    }
    __syncthreads();
    unsigned base = s_base + wsum[wid] + texcl;
    if (i0 < N_CNT) {
        uint4 o = make_uint4(base, base + t1, base + t2, base + t3);
        *reinterpret_cast<uint4*>(&g_offs[i0]) = o;
        *reinterpret_cast<uint4*>(&g_cursor[i0]) = o;
    }
}

// ---- 4. scatter (r10-identical except val stored as replicated half2) ----
__global__ void scatter_kernel(const int* __restrict__ rows,
                               const int* __restrict__ cols,
                               const float* __restrict__ vals) {
    unsigned q = blockIdx.x * blockDim.x + threadIdx.x;
    int4   r4 = __ldg(reinterpret_cast<const int4*>(rows) + q);
    int4   c4 = __ldg(reinterpret_cast<const int4*>(cols) + q);
    float4 v4 = __ldg(reinterpret_cast<const float4*>(vals) + q);
    const int*   rr = &r4.x;
    const int*   cc = &c4.x;
    const float* vv = &v4.x;
    #pragma unroll
    for (int k = 0; k < 4; k++) {
        int r = rr[k], c = cc[k];
        if (test_bit(g_s3_bits, r))
            atomicOr(&g_s2_bits[c >> 5], 1u << (c & 31));
        unsigned pos = atomicAdd(&g_cursor[r], 1u);
        __half2 h = __float2half2_rn(vv[k]);
        g_edges[pos] = make_int2(c, *reinterpret_cast<int*>(&h));
    }
}

// ---- CSR row body: THE one change vs r10 — dual-bank HFMA2 accumulation ----
__device__ __forceinline__ __half2 h2bits(int b) {
    return *reinterpret_cast<__half2*>(&b);
}

__device__ __forceinline__ void hfma4b(__half2* acc, uint4 a, __half2 v) {
    acc[0] = __hfma2(v, *reinterpret_cast<__half2*>(&a.x), acc[0]);
    acc[1] = __hfma2(v, *reinterpret_cast<__half2*>(&a.y), acc[1]);
    acc[2] = __hfma2(v, *reinterpret_cast<__half2*>(&a.z), acc[2]);
    acc[3] = __hfma2(v, *reinterpret_cast<__half2*>(&a.w), acc[3]);
}

__device__ __forceinline__ void csr_row_body(int r, const __half* __restrict__ x,
                                             __half* __restrict__ y, int lane) {
    unsigned s = __ldg(&g_offs[r]);
    unsigned n = __ldg(&g_deg[r]);
    int grp = lane >> 3, sub = lane & 7;
    const uint4* X = reinterpret_cast<const uint4*>(x);

    __half2 accA[4], accB[4];
    accA[0] = accA[1] = accA[2] = accA[3] = __float2half2_rn(0.f);
    accB[0] = accB[1] = accB[2] = accB[3] = __float2half2_rn(0.f);

    unsigned i = grp;
    for (; i + 12 < n; i += 16) {
        int2 r0 = __ldg(&g_edges[s + i]);
        int2 r1 = __ldg(&g_edges[s + i + 4]);
        int2 r2 = __ldg(&g_edges[s + i + 8]);
        int2 r3 = __ldg(&g_edges[s + i + 12]);
        uint4 a0 = __ldg(X + (size_t)r0.x * 8 + sub);
        uint4 a1 = __ldg(X + (size_t)r1.x * 8 + sub);
        uint4 a2 = __ldg(X + (size_t)r2.x * 8 + sub);
        uint4 a3 = __ldg(X + (size_t)r3.x * 8 + sub);
        hfma4b(accA, a0, h2bits(r0.y));
        hfma4b(accB, a1, h2bits(r1.y));
        hfma4b(accA, a2, h2bits(r2.y));
        hfma4b(accB, a3, h2bits(r3.y));
    }
    bool bank = false;
    for (; i < n; i += 4) {
        int2 rec = __ldg(&g_edges[s + i]);
        uint4 a = __ldg(X + (size_t)rec.x * 8 + sub);
        hfma4b(bank ? accB : accA, a, h2bits(rec.y));
        bank = !bank;
    }
    #pragma unroll
    for (int k = 0; k < 4; k++) accA[k] = __hadd2(accA[k], accB[k]);

    #pragma unroll
    for (int o = 8; o <= 16; o <<= 1) {
        #pragma unroll
        for (int k = 0; k < 4; k++) {
            unsigned u = *reinterpret_cast<unsigned*>(&accA[k]);
            unsigned p = __shfl_xor_sync(0xffffffffu, u, o);
            accA[k] = __hadd2(accA[k], *reinterpret_cast<__half2*>(&p));
        }
    }

    if (grp == 0) {
        uint4 o;
        o.x = *reinterpret_cast<unsigned*>(&accA[0]);
        o.y = *reinterpret_cast<unsigned*>(&accA[1]);
        o.z = *reinterpret_cast<unsigned*>(&accA[2]);
        o.w = *reinterpret_cast<unsigned*>(&accA[3]);
        reinterpret_cast<uint4*>(y)[(size_t)r * 8 + sub] = o;
    }
}

// ---- 5./6. CSR gather-SPMM (r10-identical) ----
__global__ void spmm_csr_kernel(const __half* __restrict__ x,
                                __half* __restrict__ y,
                                const unsigned* __restrict__ sel_bits) {
    unsigned warp = (blockIdx.x * blockDim.x + threadIdx.x) >> 5;
    if (warp >= N_CNT) return;
    int r = (int)warp;
    if (sel_bits && !test_bit(sel_bits, r)) return;
    csr_row_body(r, x, y, threadIdx.x & 31);
}

// ---- 7. layer-3: one warp per sampled row (r10-identical) ----
__global__ void spmm_rows_kernel(const int* __restrict__ users,
                                 const int* __restrict__ items,
                                 const __half* __restrict__ x,
                                 __half* __restrict__ y) {
    unsigned warp = (blockIdx.x * blockDim.x + threadIdx.x) >> 5;
    if (warp >= 2u * B_CNT) return;
    int r = (warp < B_CNT) ? __ldg(users + warp)
                           : (U_CNT + __ldg(items + (warp - B_CNT)));
    csr_row_body(r, x, y, threadIdx.x & 31);
}

// ---- 8. epilogue (r10-identical) ----
__global__ void finalize_kernel(const float* __restrict__ ue,
                                const float* __restrict__ ie,
                                const float* __restrict__ W,
                                const float* __restrict__ bias,
                                const int* __restrict__ users,
                                const int* __restrict__ items,
                                const float* __restrict__ u_his,
                                const float* __restrict__ i_his,
                                float* __restrict__ out) {
    __shared__ float sWt[DIM * DIM];
    __shared__ float s_on[2][DIM];

    int b = blockIdx.x;
    int tid = threadIdx.x;

    for (int idx = tid; idx < DIM * DIM; idx += 128) {
        int j = idx >> 6, k = idx & 63;
        sWt[k * DIM + j] = W[idx];
    }

    int half_ = tid >> 6;
    int j = tid & 63;
    int row = half_ ? __ldg(items + b) : __ldg(users + b);
    int node = half_ ? (U_CNT + row) : row;
    const float* base = half_ ? ie : ue;

    size_t gi = (size_t)row * DIM + j;
    size_t ni = (size_t)node * DIM + j;
    float on = 0.25f * (base[gi]
                        + __half2float(g_cur1h[ni])
                        + __half2float(g_cur2h[ni])
                        + __half2float(g_cur3h[ni]));
    s_on[half_][j] = on;
    __syncthreads();

    float acc = __ldg(bias + j);
    const float* onv = s_on[half_];
    #pragma unroll
    for (int k = 0; k < DIM; k++)
        acc = fmaf(onv[k], sWt[k * DIM + j], acc);

    const float* his = half_ ? i_his : u_his;
    float tgt = his[gi] * 0.05f + on * 0.95f;

    size_t seg = (size_t)B_CNT * DIM;
    out[(size_t)(half_ * 2) * seg + (size_t)b * DIM + j] = acc;
    out[(size_t)(half_ * 2 + 1) * seg + (size_t)b * DIM + j] = tgt;
}

extern "C" void kernel_launch(void* const* d_in, const int* in_sizes, int n_in,
                              void* d_out, int out_size) {
    const float* ue    = (const float*)d_in[0];
    const float* ie    = (const float*)d_in[1];
    const float* W     = (const float*)d_in[2];
    const float* bias  = (const float*)d_in[3];
    const int*   rows  = (const int*)d_in[4];
    const int*   cols  = (const int*)d_in[5];
    const float* vals  = (const float*)d_in[6];
    const int*   users = (const int*)d_in[7];
    const int*   items = (const int*)d_in[8];
    const float* u_his = (const float*)d_in[9];
    const float* i_his = (const float*)d_in[10];
    float* out = (float*)d_out;

    __half *egoh, *c1h, *c2h, *c3h;
    cudaGetSymbolAddress((void**)&egoh, g_egoh);
    cudaGetSymbolAddress((void**)&c1h, g_cur1h);
    cudaGetSymbolAddress((void**)&c2h, g_cur2h);
    cudaGetSymbolAddress((void**)&c3h, g_cur3h);
    unsigned *s2b;
    cudaGetSymbolAddress((void**)&s2b, g_s2_bits);

    // 1. init
    {
        unsigned n16 = (unsigned)N_CNT * DIM / 8;
        init_kernel<<<(n16 + 255) / 256, 256>>>(ue, ie);
    }
    // 2. prep + hist
    prep_hist_kernel<<<HIST_BLKS + PREP_BLKS, 256>>>(rows, users, items);
    // 3. scan
    scan_kernel<<<(N_CNT + 4095) / 4096, 1024>>>();
    // 4. scatter
    scatter_kernel<<<NNZ_CNT / 1024, 256>>>(rows, cols, vals);

    unsigned csr_blocks = ((unsigned)N_CNT * 32 + 255) / 256;
    // 5. layer 1
    spmm_csr_kernel<<<csr_blocks, 256>>>(egoh, c1h, (const unsigned*)nullptr);
    // 6. layer 2 (S2)
    spmm_csr_kernel<<<csr_blocks, 256>>>(c1h, c2h, s2b);
    // 7. layer 3 (sampled rows)
    spmm_rows_kernel<<<(2 * B_CNT * 32 + 255) / 256, 256>>>(users, items, c2h, c3h);
    // 8. epilogue
    finalize_kernel<<<B_CNT, 128>>>(ue, ie, W, bias, users, items, u_his, i_his, out);
}

// round 17
// speedup vs baseline: 1.3625x; 1.3625x over previous
#include <cuda_runtime.h>
#include <cuda_fp16.h>

#define U_CNT 100000
#define I_CNT 50000
#define N_CNT 150000
#define DIM   64
#define NNZ_CNT 3200000
#define B_CNT 4096
#define NBW   ((N_CNT + 31) / 32)
#define HIST_BLKS (NNZ_CNT / 1024)      // 3125
#define PREP_BLKS ((2 * B_CNT + 255) / 256)  // 32

// ---- scratch (__device__ globals; allocation-free rule) ----
__device__ __align__(16) __half g_egoh[N_CNT * DIM];
__device__ __align__(16) __half g_cur1h[N_CNT * DIM];
__device__ __align__(16) __half g_cur2h[N_CNT * DIM];
__device__ __align__(16) __half g_cur3h[N_CNT * DIM];

__device__ unsigned g_s3_bits[NBW];
__device__ unsigned g_s2_bits[NBW];

// CSR structures
__device__ __align__(16) unsigned g_deg[N_CNT];
__device__ __align__(16) unsigned g_offs[N_CNT];
__device__ __align__(16) unsigned g_cursor[N_CNT];
__device__ unsigned g_total;
__device__ __align__(16) int2     g_edges[NNZ_CNT];   // {col, val_bits}

__device__ __forceinline__ bool test_bit(const unsigned* bits, int n) {
    return (__ldg(bits + (n >> 5)) >> (n & 31)) & 1u;
}

// ---- 1. init: convert ego to fp16, zero deg/bitmaps/total ----
__global__ void init_kernel(const float* __restrict__ ue,
                            const float* __restrict__ ie) {
    unsigned t = blockIdx.x * blockDim.x + threadIdx.x;
    const unsigned n16 = (unsigned)N_CNT * DIM / 8;
    if (t < n16) {
        const unsigned UF4 = (unsigned)U_CNT * DIM / 4;
        unsigned f0 = 2u * t, f1 = 2u * t + 1u;
        float4 a = (f0 < UF4) ? __ldg(reinterpret_cast<const float4*>(ue) + f0)
                              : __ldg(reinterpret_cast<const float4*>(ie) + (f0 - UF4));
        float4 b = (f1 < UF4) ? __ldg(reinterpret_cast<const float4*>(ue) + f1)
                              : __ldg(reinterpret_cast<const float4*>(ie) + (f1 - UF4));
        uint4 o;
        __half2 h;
        h = __floats2half2_rn(a.x, a.y); o.x = *reinterpret_cast<unsigned*>(&h);
        h = __floats2half2_rn(a.z, a.w); o.y = *reinterpret_cast<unsigned*>(&h);
        h = __floats2half2_rn(b.x, b.y); o.z = *reinterpret_cast<unsigned*>(&h);
        h = __floats2half2_rn(b.z, b.w); o.w = *reinterpret_cast<unsigned*>(&h);
        reinterpret_cast<uint4*>(g_egoh)[t] = o;
    }
    if (t < N_CNT / 4)
        reinterpret_cast<uint4*>(g_deg)[t] = make_uint4(0u, 0u, 0u, 0u);
    if (t < NBW) { g_s3_bits[t] = 0u; g_s2_bits[t] = 0u; }
    if (t == 0) g_total = 0u;
}

// ---- 2. prep + hist merged (disjoint block ranges) ----
__global__ void prep_hist_kernel(const int* __restrict__ rows,
                                 const int* __restrict__ users,
                                 const int* __restrict__ items) {
    unsigned b = blockIdx.x;
    if (b < HIST_BLKS) {
        unsigned q = b * 256u + threadIdx.x;
        int4 r4 = __ldg(reinterpret_cast<const int4*>(rows) + q);
        atomicAdd(&g_deg[r4.x], 1u);
        atomicAdd(&g_deg[r4.y], 1u);
        atomicAdd(&g_deg[r4.z], 1u);
        atomicAdd(&g_deg[r4.w], 1u);
    } else {
        unsigned t = (b - HIST_BLKS) * 256u + threadIdx.x;
        if (t < 2u * B_CNT) {
            int node = (t < B_CNT) ? __ldg(users + t)
                                   : (U_CNT + __ldg(items + (t - B_CNT)));
            atomicOr(&g_s3_bits[node >> 5], 1u << (node & 31));
            atomicOr(&g_s2_bits[node >> 5], 1u << (node & 31));
        }
    }
}

// ---- 3. single-kernel scan: intra-block prefix + atomic global base ----
// Segment placement is block-arrival-ordered; CSR semantics don't care.
__global__ void scan_kernel() {
    __shared__ unsigned wsum[32];
    __shared__ unsigned s_base;
    int tid = threadIdx.x, lane = tid & 31, wid = tid >> 5;
    unsigned i0 = blockIdx.x * 4096u + tid * 4u;
    uint4 d = make_uint4(0u, 0u, 0u, 0u);
    if (i0 < N_CNT) d = *reinterpret_cast<const uint4*>(&g_deg[i0]);
    unsigned t1 = d.x, t2 = d.x + d.y, t3 = d.x + d.y + d.z;
    unsigned tsum = t3 + d.w;
    unsigned inc = tsum;
    #pragma unroll
    for (int o = 1; o < 32; o <<= 1) {
        unsigned v = __shfl_up_sync(0xffffffffu, inc, o);
        if (lane >= o) inc += v;
    }
    unsigned texcl = inc - tsum;
    if (lane == 31) wsum[wid] = inc;
    __syncthreads();
    if (wid == 0) {
        unsigned ws = wsum[lane];
        unsigned wi = ws;
        #pragma unroll
        for (int o = 1; o < 32; o <<= 1) {
            unsigned v = __shfl_up_sync(0xffffffffu, wi, o);
            if (lane >= o) wi += v;
        }
        if (lane == 31) s_base = atomicAdd(&g_total, wi);  // block total
        wsum[lane] = wi - ws;
    }
    __syncthreads();
    unsigned base = s_base + wsum[wid] + texcl;
    if (i0 < N_CNT) {
        uint4 o = make_uint4(base, base + t1, base + t2, base + t3);
        *reinterpret_cast<uint4*>(&g_offs[i0]) = o;
        *reinterpret_cast<uint4*>(&g_cursor[i0]) = o;
    }
}

// ---- 4. scatter edges into CSR + S2 marking ----
__global__ void scatter_kernel(const int* __restrict__ rows,
                               const int* __restrict__ cols,
                               const float* __restrict__ vals) {
    unsigned q = blockIdx.x * blockDim.x + threadIdx.x;
    int4   r4 = __ldg(reinterpret_cast<const int4*>(rows) + q);
    int4   c4 = __ldg(reinterpret_cast<const int4*>(cols) + q);
    float4 v4 = __ldg(reinterpret_cast<const float4*>(vals) + q);
    const int*   rr = &r4.x;
    const int*   cc = &c4.x;
    const float* vv = &v4.x;
    #pragma unroll
    for (int k = 0; k < 4; k++) {
        int r = rr[k], c = cc[k];
        if (test_bit(g_s3_bits, r))
            atomicOr(&g_s2_bits[c >> 5], 1u << (c & 31));
        unsigned pos = atomicAdd(&g_cursor[r], 1u);
        g_edges[pos] = make_int2(c, __float_as_int(vv[k]));
    }
}

// ---- CSR row body: 4 edge-groups x 8 lanes, depth-4 pipeline ----
__device__ __forceinline__ void fma8(float* acc, uint4 a, float v) {
    __half2 h; float2 f;
    h = *reinterpret_cast<__half2*>(&a.x); f = __half22float2(h);
    acc[0] = fmaf(v, f.x, acc[0]); acc[1] = fmaf(v, f.y, acc[1]);
    h = *reinterpret_cast<__half2*>(&a.y); f = __half22float2(h);
    acc[2] = fmaf(v, f.x, acc[2]); acc[3] = fmaf(v, f.y, acc[3]);
    h = *reinterpret_cast<__half2*>(&a.z); f = __half22float2(h);
    acc[4] = fmaf(v, f.x, acc[4]); acc[5] = fmaf(v, f.y, acc[5]);
    h = *reinterpret_cast<__half2*>(&a.w); f = __half22float2(h);
    acc[6] = fmaf(v, f.x, acc[6]); acc[7] = fmaf(v, f.y, acc[7]);
}

__device__ __forceinline__ void csr_row_body(int r, const __half* __restrict__ x,
                                             __half* __restrict__ y, int lane) {
    unsigned s = __ldg(&g_offs[r]);
    unsigned n = __ldg(&g_deg[r]);
    int grp = lane >> 3, sub = lane & 7;
    const uint4* X = reinterpret_cast<const uint4*>(x);

    float acc[8];
    #pragma unroll
    for (int k = 0; k < 8; k++) acc[k] = 0.f;

    unsigned i = grp;
    for (; i + 12 < n; i += 16) {
        int2 r0 = __ldg(&g_edges[s + i]);
        int2 r1 = __ldg(&g_edges[s + i + 4]);
        int2 r2 = __ldg(&g_edges[s + i + 8]);
        int2 r3 = __ldg(&g_edges[s + i + 12]);
        uint4 a0 = __ldg(X + (size_t)r0.x * 8 + sub);
        uint4 a1 = __ldg(X + (size_t)r1.x * 8 + sub);
        uint4 a2 = __ldg(X + (size_t)r2.x * 8 + sub);
        uint4 a3 = __ldg(X + (size_t)r3.x * 8 + sub);
        fma8(acc, a0, __int_as_float(r0.y));
        fma8(acc, a1, __int_as_float(r1.y));
        fma8(acc, a2, __int_as_float(r2.y));
        fma8(acc, a3, __int_as_float(r3.y));
    }
    for (; i < n; i += 4) {
        int2 rec = __ldg(&g_edges[s + i]);
        uint4 a = __ldg(X + (size_t)rec.x * 8 + sub);
        fma8(acc, a, __int_as_float(rec.y));
    }

    #pragma unroll
    for (int o = 8; o <= 16; o <<= 1) {
        #pragma unroll
        for (int k = 0; k < 8; k++)
            acc[k] += __shfl_xor_sync(0xffffffffu, acc[k], o);
    }

    if (grp == 0) {
        uint4 o;
        __half2 h;
        h = __floats2half2_rn(acc[0], acc[1]); o.x = *reinterpret_cast<unsigned*>(&h);
        h = __floats2half2_rn(acc[2], acc[3]); o.y = *reinterpret_cast<unsigned*>(&h);
        h = __floats2half2_rn(acc[4], acc[5]); o.z = *reinterpret_cast<unsigned*>(&h);
        h = __floats2half2_rn(acc[6], acc[7]); o.w = *reinterpret_cast<unsigned*>(&h);
        reinterpret_cast<uint4*>(y)[(size_t)r * 8 + sub] = o;
    }
}

// ---- 5./6. CSR gather-SPMM ----
__global__ void spmm_csr_kernel(const __half* __restrict__ x,
                                __half* __restrict__ y,
                                const unsigned* __restrict__ sel_bits) {
    unsigned warp = (blockIdx.x * blockDim.x + threadIdx.x) >> 5;
    if (warp >= N_CNT) return;
    int r = (int)warp;
    if (sel_bits && !test_bit(sel_bits, r)) return;
    csr_row_body(r, x, y, threadIdx.x & 31);
}

// ---- 7. layer-3: one warp per sampled row ----
__global__ void spmm_rows_kernel(const int* __restrict__ users,
                                 const int* __restrict__ items,
                                 const __half* __restrict__ x,
                                 __half* __restrict__ y) {
    unsigned warp = (blockIdx.x * blockDim.x + threadIdx.x) >> 5;
    if (warp >= 2u * B_CNT) return;
    int r = (warp < B_CNT) ? __ldg(users + warp)
                           : (U_CNT + __ldg(items + (warp - B_CNT)));
    csr_row_body(r, x, y, threadIdx.x & 31);
}

// ---- 8. epilogue ----
__global__ void finalize_kernel(const float* __restrict__ ue,
                                const float* __restrict__ ie,
                                const float* __restrict__ W,
                                const float* __restrict__ bias,
                                const int* __restrict__ users,
                                const int* __restrict__ items,
                                const float* __restrict__ u_his,
                                const float* __restrict__ i_his,
                                float* __restrict__ out) {
    __shared__ float sWt[DIM * DIM];
    __shared__ float s_on[2][DIM];

    int b = blockIdx.x;
    int tid = threadIdx.x;

    for (int idx = tid; idx < DIM * DIM; idx += 128) {
        int j = idx >> 6, k = idx & 63;
        sWt[k * DIM + j] = W[idx];
    }

    int half_ = tid >> 6;
    int j = tid & 63;
    int row = half_ ? __ldg(items + b) : __ldg(users + b);
    int node = half_ ? (U_CNT + row) : row;
    const float* base = half_ ? ie : ue;

    size_t gi = (size_t)row * DIM + j;
    size_t ni = (size_t)node * DIM + j;
    float on = 0.25f * (base[gi]
                        + __half2float(g_cur1h[ni])
                        + __half2float(g_cur2h[ni])
                        + __half2float(g_cur3h[ni]));
    s_on[half_][j] = on;
    __syncthreads();

    float acc = __ldg(bias + j);
    const float* onv = s_on[half_];
    #pragma unroll
    for (int k = 0; k < DIM; k++)
        acc = fmaf(onv[k], sWt[k * DIM + j], acc);

    const float* his = half_ ? i_his : u_his;
    float tgt = his[gi] * 0.05f + on * 0.95f;

    size_t seg = (size_t)B_CNT * DIM;
    out[(size_t)(half_ * 2) * seg + (size_t)b * DIM + j] = acc;
    out[(size_t)(half_ * 2 + 1) * seg + (size_t)b * DIM + j] = tgt;
}

extern "C" void kernel_launch(void* const* d_in, const int* in_sizes, int n_in,
                              void* d_out, int out_size) {
    const float* ue    = (const float*)d_in[0];
    const float* ie    = (const float*)d_in[1];
    const float* W     = (const float*)d_in[2];
    const float* bias  = (const float*)d_in[3];
    const int*   rows  = (const int*)d_in[4];
    const int*   cols  = (const int*)d_in[5];
    const float* vals  = (const float*)d_in[6];
    const int*   users = (const int*)d_in[7];
    const int*   items = (const int*)d_in[8];
    const float* u_his = (const float*)d_in[9];
    const float* i_his = (const float*)d_in[10];
    float* out = (float*)d_out;

    __half *egoh, *c1h, *c2h, *c3h;
    cudaGetSymbolAddress((void**)&egoh, g_egoh);
    cudaGetSymbolAddress((void**)&c1h, g_cur1h);
    cudaGetSymbolAddress((void**)&c2h, g_cur2h);
    cudaGetSymbolAddress((void**)&c3h, g_cur3h);
    unsigned *s2b;
    cudaGetSymbolAddress((void**)&s2b, g_s2_bits);

    // 1. init
    {
        unsigned n16 = (unsigned)N_CNT * DIM / 8;
        init_kernel<<<(n16 + 255) / 256, 256>>>(ue, ie);
    }
    // 2. prep + hist
    prep_hist_kernel<<<HIST_BLKS + PREP_BLKS, 256>>>(rows, users, items);
    // 3. scan (single kernel, atomic base)
    scan_kernel<<<(N_CNT + 4095) / 4096, 1024>>>();
    // 4. scatter  (profiler slot)
    scatter_kernel<<<NNZ_CNT / 1024, 256>>>(rows, cols, vals);

    unsigned csr_blocks = ((unsigned)N_CNT * 32 + 255) / 256;
    // 5. layer 1
    spmm_csr_kernel<<<csr_blocks, 256>>>(egoh, c1h, (const unsigned*)nullptr);
    // 6. layer 2 (S2)
    spmm_csr_kernel<<<csr_blocks, 256>>>(c1h, c2h, s2b);
    // 7. layer 3 (sampled rows)
    spmm_rows_kernel<<<(2 * B_CNT * 32 + 255) / 256, 256>>>(users, items, c2h, c3h);
    // 8. epilogue
    finalize_kernel<<<B_CNT, 128>>>(ue, ie, W, bias, users, items, u_his, i_his, out);
}